// round 1
// baseline (speedup 1.0000x reference)
#include <cuda_runtime.h>
#include <math.h>

#define BATCH 2048
#define LAT   16
#define NC    23
#define HID0  16
#define HID1  32
#define NOUT  4000
#define CH    (NC*HID0)   // 368
#define CZ    (NC*HID1)   // 736
#define OUTW  (NC*NOUT)   // 92000
#define EPSN  1e-5f

#define NB1 64
#define NB3 64

// ---------------- scratch (device globals; no allocation) ----------------
__device__ float g_p1[NB1][272];        // per-block partial: sum_x[16], sum_xx[256]
__device__ float g_a1[CH], g_c1[CH];    // fused BN1 scale/shift
__device__ float g_z[BATCH*CZ];         // pre-BN z   [2048, 736]
__device__ float g_p3[NB3][2*CZ];       // per-block partial sum / sumsq of z
__device__ float g_a0[CZ], g_c0[CZ];    // fused BN0 scale/shift

// ---------------- K1: partial stats of x (sum, sum of outer products) -----
__global__ void k1_xstats(const float* __restrict__ x) {
    __shared__ float sx[32][LAT];
    int t = threadIdx.x;                 // 256 threads
    int r0 = blockIdx.x * 32;
    for (int i = t; i < 32*LAT; i += 256)
        sx[i >> 4][i & 15] = x[(r0 + (i >> 4))*LAT + (i & 15)];
    __syncthreads();
    int i = t >> 4, j = t & 15;
    float s = 0.f;
    #pragma unroll
    for (int r = 0; r < 32; r++) s += sx[r][i] * sx[r][j];
    g_p1[blockIdx.x][16 + t] = s;
    if (t < 16) {
        float sm = 0.f;
        #pragma unroll
        for (int r = 0; r < 32; r++) sm += sx[r][t];
        g_p1[blockIdx.x][t] = sm;
    }
}

// ---------------- K2: h-stats from x-stats (exact: h is linear in x) ------
__global__ void k2_bn1(const float* __restrict__ W1, const float* __restrict__ b1,
                       const float* __restrict__ g1, const float* __restrict__ be1) {
    __shared__ float raw[272];
    __shared__ float smu[16];
    __shared__ float scov[256];
    int t = threadIdx.x;                 // 512 threads
    if (t < 272) {
        float s = 0.f;
        for (int b = 0; b < NB1; b++) s += g_p1[b][t];
        raw[t] = s;
    }
    __syncthreads();
    if (t < 16) smu[t] = raw[t] * (1.f/BATCH);
    __syncthreads();
    if (t < 256) scov[t] = raw[16 + t] * (1.f/BATCH) - smu[t >> 4]*smu[t & 15];
    __syncthreads();
    for (int j = t; j < CH; j += 512) {
        float w[16];
        #pragma unroll
        for (int i = 0; i < 16; i++) w[i] = __ldg(&W1[j*16 + i]);
        float m = __ldg(&b1[j]);
        #pragma unroll
        for (int i = 0; i < 16; i++) m = fmaf(w[i], smu[i], m);
        float v = 0.f;
        #pragma unroll
        for (int i = 0; i < 16; i++) {
            float wi = w[i];
            #pragma unroll
            for (int k = 0; k < 16; k++) v = fmaf(wi * w[k], scov[i*16 + k], v);
        }
        float a = __ldg(&g1[j]) * rsqrtf(v + EPSN);
        g_a1[j] = a;
        g_c1[j] = __ldg(&be1[j]) - m * a;
    }
}

// ---------------- K3: h -> BN1+leaky -> grouped 16->32 -> z + partial stats
__global__ __launch_bounds__(256) void k3_z(
    const float* __restrict__ x, const float* __restrict__ W1,
    const float* __restrict__ b1, const float* __restrict__ W0,
    const float* __restrict__ b0) {
    __shared__ __align__(16) float shn[32][CH];   // 47104 B
    int t = threadIdx.x;
    int r0 = blockIdx.x * 32;
    // phase 1: hn = leaky(a1*h + c1) for 32 rows x 368 cols
    for (int idx = t; idx < 32*CH; idx += 256) {
        int row = idx / CH, j = idx - row*CH;
        const float4* wp = (const float4*)(W1 + j*16);
        const float4* xp = (const float4*)(x + (size_t)(r0 + row)*16);
        float4 w0 = __ldg(wp+0), w1 = __ldg(wp+1), w2 = __ldg(wp+2), w3 = __ldg(wp+3);
        float4 x0 = __ldg(xp+0), x1 = __ldg(xp+1), x2 = __ldg(xp+2), x3 = __ldg(xp+3);
        float h = __ldg(&b1[j]);
        h = fmaf(w0.x,x0.x, fmaf(w0.y,x0.y, fmaf(w0.z,x0.z, fmaf(w0.w,x0.w, h))));
        h = fmaf(w1.x,x1.x, fmaf(w1.y,x1.y, fmaf(w1.z,x1.z, fmaf(w1.w,x1.w, h))));
        h = fmaf(w2.x,x2.x, fmaf(w2.y,x2.y, fmaf(w2.z,x2.z, fmaf(w2.w,x2.w, h))));
        h = fmaf(w3.x,x3.x, fmaf(w3.y,x3.y, fmaf(w3.z,x3.z, fmaf(w3.w,x3.w, h))));
        float v = fmaf(h, g_a1[j], g_c1[j]);
        shn[row][j] = v >= 0.f ? v : 0.2f*v;
    }
    __syncthreads();
    // phase 2: z = hn @ W0^T (per chromosome), write z + per-block stats
    for (int cc = t; cc < CZ; cc += 256) {
        int c = cc >> 5, o = cc & 31;
        const float4* wp = (const float4*)(W0 + (size_t)(c*32 + o)*16);
        float4 w0 = __ldg(wp+0), w1 = __ldg(wp+1), w2 = __ldg(wp+2), w3 = __ldg(wp+3);
        float bb = __ldg(&b0[cc]);
        float s1 = 0.f, s2 = 0.f;
        #pragma unroll 4
        for (int row = 0; row < 32; row++) {
            const float4* hp = (const float4*)&shn[row][c*16];
            float4 h0 = hp[0], h1 = hp[1], h2 = hp[2], h3 = hp[3];
            float z = bb;
            z = fmaf(w0.x,h0.x, fmaf(w0.y,h0.y, fmaf(w0.z,h0.z, fmaf(w0.w,h0.w, z))));
            z = fmaf(w1.x,h1.x, fmaf(w1.y,h1.y, fmaf(w1.z,h1.z, fmaf(w1.w,h1.w, z))));
            z = fmaf(w2.x,h2.x, fmaf(w2.y,h2.y, fmaf(w2.z,h2.z, fmaf(w2.w,h2.w, z))));
            z = fmaf(w3.x,h3.x, fmaf(w3.y,h3.y, fmaf(w3.z,h3.z, fmaf(w3.w,h3.w, z))));
            g_z[(size_t)(r0 + row)*CZ + cc] = z;
            s1 += z; s2 = fmaf(z, z, s2);
        }
        g_p3[blockIdx.x][cc]      = s1;
        g_p3[blockIdx.x][CZ + cc] = s2;
    }
}

// ---------------- K4: reduce z stats -> fused BN0 scale/shift -------------
__global__ void k4_bn0(const float* __restrict__ g0, const float* __restrict__ bb0) {
    int t = threadIdx.x;                 // 768 threads
    if (t < CZ) {
        float s1 = 0.f, s2 = 0.f;
        for (int b = 0; b < NB3; b++) { s1 += g_p3[b][t]; s2 += g_p3[b][CZ + t]; }
        float mu  = s1 * (1.f/BATCH);
        float var = s2 * (1.f/BATCH) - mu*mu;
        float a = __ldg(&g0[t]) * rsqrtf(var + EPSN);
        g_a0[t] = a;
        g_c0[t] = __ldg(&bb0[t]) - mu * a;
    }
}

// ---------------- K5: grouped 32->4000 GEMM + sigmoid ---------------------
__device__ __forceinline__ float sigf(float v) {
    return __fdividef(1.f, 1.f + __expf(-v));
}

__global__ __launch_bounds__(256) void k5_gemm(
    const float* __restrict__ W2, const float* __restrict__ b2,
    float* __restrict__ out) {
    __shared__ __align__(16) float As[32][64];   // k-major zn tile
    __shared__ __align__(16) float Bs[32][64];   // k-major W2 tile
    int t  = threadIdx.x;
    int c  = blockIdx.z;
    int m0 = blockIdx.y * 64;
    int n0 = blockIdx.x * 64;

    // load A (zn = leaky(a0*z + c0), applied on the fly)
    #pragma unroll
    for (int s = 0; s < 2; s++) {
        int idx = t + s*256;
        int r = idx >> 3, kq = idx & 7;
        float4 z4 = *(const float4*)&g_z[(size_t)(m0 + r)*CZ + c*32 + kq*4];
        float4 a4 = *(const float4*)&g_a0[c*32 + kq*4];
        float4 c4 = *(const float4*)&g_c0[c*32 + kq*4];
        float v0 = fmaf(z4.x, a4.x, c4.x); v0 = v0 >= 0.f ? v0 : 0.2f*v0;
        float v1 = fmaf(z4.y, a4.y, c4.y); v1 = v1 >= 0.f ? v1 : 0.2f*v1;
        float v2 = fmaf(z4.z, a4.z, c4.z); v2 = v2 >= 0.f ? v2 : 0.2f*v2;
        float v3 = fmaf(z4.w, a4.w, c4.w); v3 = v3 >= 0.f ? v3 : 0.2f*v3;
        As[kq*4+0][r] = v0; As[kq*4+1][r] = v1;
        As[kq*4+2][r] = v2; As[kq*4+3][r] = v3;
    }
    // load B (guard n>=4000 on the last tile)
    #pragma unroll
    for (int s = 0; s < 2; s++) {
        int idx = t + s*256;
        int r = idx >> 3, kq = idx & 7;
        int o = n0 + r;
        float4 w4 = make_float4(0.f, 0.f, 0.f, 0.f);
        if (o < NOUT)
            w4 = *(const float4*)&W2[((size_t)c*NOUT + o)*32 + kq*4];
        Bs[kq*4+0][r] = w4.x; Bs[kq*4+1][r] = w4.y;
        Bs[kq*4+2][r] = w4.z; Bs[kq*4+3][r] = w4.w;
    }
    __syncthreads();

    int tx = t & 15, ty = t >> 4;
    float acc[4][4] = {};
    #pragma unroll
    for (int k = 0; k < 32; k++) {
        float4 a = *(const float4*)&As[k][ty*4];
        float4 b = *(const float4*)&Bs[k][tx*4];
        acc[0][0] = fmaf(a.x, b.x, acc[0][0]); acc[0][1] = fmaf(a.x, b.y, acc[0][1]);
        acc[0][2] = fmaf(a.x, b.z, acc[0][2]); acc[0][3] = fmaf(a.x, b.w, acc[0][3]);
        acc[1][0] = fmaf(a.y, b.x, acc[1][0]); acc[1][1] = fmaf(a.y, b.y, acc[1][1]);
        acc[1][2] = fmaf(a.y, b.z, acc[1][2]); acc[1][3] = fmaf(a.y, b.w, acc[1][3]);
        acc[2][0] = fmaf(a.z, b.x, acc[2][0]); acc[2][1] = fmaf(a.z, b.y, acc[2][1]);
        acc[2][2] = fmaf(a.z, b.z, acc[2][2]); acc[2][3] = fmaf(a.z, b.w, acc[2][3]);
        acc[3][0] = fmaf(a.w, b.x, acc[3][0]); acc[3][1] = fmaf(a.w, b.y, acc[3][1]);
        acc[3][2] = fmaf(a.w, b.z, acc[3][2]); acc[3][3] = fmaf(a.w, b.w, acc[3][3]);
    }

    int n = n0 + tx*4;
    if (n < NOUT) {
        float4 bias = *(const float4*)&b2[(size_t)c*NOUT + n];
        #pragma unroll
        for (int i = 0; i < 4; i++) {
            int m = m0 + ty*4 + i;
            float4 r;
            r.x = sigf(acc[i][0] + bias.x);
            r.y = sigf(acc[i][1] + bias.y);
            r.z = sigf(acc[i][2] + bias.z);
            r.w = sigf(acc[i][3] + bias.w);
            *(float4*)&out[(size_t)m*OUTW + (size_t)c*NOUT + n] = r;
        }
    }
}

// ---------------- launch ---------------------------------------------------
extern "C" void kernel_launch(void* const* d_in, const int* in_sizes, int n_in,
                              void* d_out, int out_size) {
    const float* x   = (const float*)d_in[0];
    const float* W1  = (const float*)d_in[1];
    const float* b1  = (const float*)d_in[2];
    const float* g1  = (const float*)d_in[3];
    const float* be1 = (const float*)d_in[4];
    const float* W0  = (const float*)d_in[5];
    const float* b0  = (const float*)d_in[6];
    const float* g0  = (const float*)d_in[7];
    const float* bb0 = (const float*)d_in[8];
    const float* W2  = (const float*)d_in[9];
    const float* b2  = (const float*)d_in[10];
    float* out = (float*)d_out;

    k1_xstats<<<NB1, 256>>>(x);
    k2_bn1<<<1, 512>>>(W1, b1, g1, be1);
    k3_z<<<NB3, 256>>>(x, W1, b1, W0, b0);
    k4_bn0<<<1, 768>>>(g0, bb0);
    k5_gemm<<<dim3((NOUT + 63)/64, BATCH/64, NC), 256>>>(W2, b2, out);
}

// round 3
// speedup vs baseline: 1.3292x; 1.3292x over previous
#include <cuda_runtime.h>
#include <cstdint>
#include <math.h>

#define BATCH 2048
#define LAT   16
#define NC    23
#define HID0  16
#define HID1  32
#define NOUT  4000
#define CH    (NC*HID0)   // 368
#define CZ    (NC*HID1)   // 736
#define OUTW  (NC*NOUT)   // 92000
#define EPSN  1e-5f

#define NB1 64
#define NB3 64

// ---------------- scratch (device globals; no allocation) ----------------
__device__ float g_p1[NB1][272];                  // per-block: sum_x[16], sum_xx[256]
__device__ __align__(16) float g_a1[CH], g_c1[CH];
__device__ __align__(16) float g_z[BATCH*CZ];     // pre-BN z   [2048, 736]
__device__ float g_p3[NB3][2*CZ];
__device__ __align__(16) float g_a0[CZ], g_c0[CZ];

// ---------------- K1: partial stats of x ----------------------------------
__global__ void k1_xstats(const float* __restrict__ x) {
    __shared__ float sx[32][LAT];
    int t = threadIdx.x;
    int r0 = blockIdx.x * 32;
    for (int i = t; i < 32*LAT; i += 256)
        sx[i >> 4][i & 15] = x[(r0 + (i >> 4))*LAT + (i & 15)];
    __syncthreads();
    int i = t >> 4, j = t & 15;
    float s = 0.f;
    #pragma unroll
    for (int r = 0; r < 32; r++) s += sx[r][i] * sx[r][j];
    g_p1[blockIdx.x][16 + t] = s;
    if (t < 16) {
        float sm = 0.f;
        #pragma unroll
        for (int r = 0; r < 32; r++) sm += sx[r][t];
        g_p1[blockIdx.x][t] = sm;
    }
}

// ---------------- K2: h-stats from x-stats (h linear in x) -----------------
__global__ void k2_bn1(const float* __restrict__ W1, const float* __restrict__ b1,
                       const float* __restrict__ g1, const float* __restrict__ be1) {
    __shared__ float raw[272];
    __shared__ float smu[16];
    __shared__ float scov[256];
    int t = threadIdx.x;                 // 512
    if (t < 272) {
        float s = 0.f;
        #pragma unroll 8
        for (int b = 0; b < NB1; b++) s += g_p1[b][t];
        raw[t] = s;
    }
    __syncthreads();
    if (t < 16) smu[t] = raw[t] * (1.f/BATCH);
    __syncthreads();
    if (t < 256) scov[t] = raw[16 + t] * (1.f/BATCH) - smu[t >> 4]*smu[t & 15];
    __syncthreads();
    for (int j = t; j < CH; j += 512) {
        float w[16];
        #pragma unroll
        for (int i = 0; i < 16; i++) w[i] = __ldg(&W1[j*16 + i]);
        float m = __ldg(&b1[j]);
        #pragma unroll
        for (int i = 0; i < 16; i++) m = fmaf(w[i], smu[i], m);
        float v = 0.f;
        #pragma unroll
        for (int i = 0; i < 16; i++) {
            float wi = w[i];
            #pragma unroll
            for (int k = 0; k < 16; k++) v = fmaf(wi * w[k], scov[i*16 + k], v);
        }
        float a = __ldg(&g1[j]) * rsqrtf(v + EPSN);
        g_a1[j] = a;
        g_c1[j] = __ldg(&be1[j]) - m * a;
    }
}

// ---------------- K3: BN1+leaky -> grouped 16->32 -> z + partial stats -----
__global__ __launch_bounds__(256) void k3_z(
    const float* __restrict__ x, const float* __restrict__ W1,
    const float* __restrict__ b1, const float* __restrict__ W0,
    const float* __restrict__ b0) {
    __shared__ __align__(16) float shn[32][CH];
    int t = threadIdx.x;
    int r0 = blockIdx.x * 32;
    for (int idx = t; idx < 32*CH; idx += 256) {
        int row = idx / CH, j = idx - row*CH;
        const float4* wp = (const float4*)(W1 + j*16);
        const float4* xp = (const float4*)(x + (size_t)(r0 + row)*16);
        float4 w0 = __ldg(wp+0), w1 = __ldg(wp+1), w2 = __ldg(wp+2), w3 = __ldg(wp+3);
        float4 x0 = __ldg(xp+0), x1 = __ldg(xp+1), x2 = __ldg(xp+2), x3 = __ldg(xp+3);
        float h = __ldg(&b1[j]);
        h = fmaf(w0.x,x0.x, fmaf(w0.y,x0.y, fmaf(w0.z,x0.z, fmaf(w0.w,x0.w, h))));
        h = fmaf(w1.x,x1.x, fmaf(w1.y,x1.y, fmaf(w1.z,x1.z, fmaf(w1.w,x1.w, h))));
        h = fmaf(w2.x,x2.x, fmaf(w2.y,x2.y, fmaf(w2.z,x2.z, fmaf(w2.w,x2.w, h))));
        h = fmaf(w3.x,x3.x, fmaf(w3.y,x3.y, fmaf(w3.z,x3.z, fmaf(w3.w,x3.w, h))));
        float v = fmaf(h, g_a1[j], g_c1[j]);
        shn[row][j] = v >= 0.f ? v : 0.2f*v;
    }
    __syncthreads();
    for (int cc = t; cc < CZ; cc += 256) {
        int c = cc >> 5, o = cc & 31;
        const float4* wp = (const float4*)(W0 + (size_t)(c*32 + o)*16);
        float4 w0 = __ldg(wp+0), w1 = __ldg(wp+1), w2 = __ldg(wp+2), w3 = __ldg(wp+3);
        float bb = __ldg(&b0[cc]);
        float s1 = 0.f, s2 = 0.f;
        #pragma unroll 4
        for (int row = 0; row < 32; row++) {
            const float4* hp = (const float4*)&shn[row][c*16];
            float4 h0 = hp[0], h1 = hp[1], h2 = hp[2], h3 = hp[3];
            float z = bb;
            z = fmaf(w0.x,h0.x, fmaf(w0.y,h0.y, fmaf(w0.z,h0.z, fmaf(w0.w,h0.w, z))));
            z = fmaf(w1.x,h1.x, fmaf(w1.y,h1.y, fmaf(w1.z,h1.z, fmaf(w1.w,h1.w, z))));
            z = fmaf(w2.x,h2.x, fmaf(w2.y,h2.y, fmaf(w2.z,h2.z, fmaf(w2.w,h2.w, z))));
            z = fmaf(w3.x,h3.x, fmaf(w3.y,h3.y, fmaf(w3.z,h3.z, fmaf(w3.w,h3.w, z))));
            g_z[(size_t)(r0 + row)*CZ + cc] = z;
            s1 += z; s2 = fmaf(z, z, s2);
        }
        g_p3[blockIdx.x][cc]      = s1;
        g_p3[blockIdx.x][CZ + cc] = s2;
    }
}

// ---------------- K4: reduce z stats -> fused BN0 scale/shift --------------
__global__ void k4_bn0(const float* __restrict__ g0, const float* __restrict__ bb0) {
    int t = threadIdx.x;                 // 768
    if (t < CZ) {
        float s1 = 0.f, s2 = 0.f;
        #pragma unroll 8
        for (int b = 0; b < NB3; b++) { s1 += g_p3[b][t]; s2 += g_p3[b][CZ + t]; }
        float mu  = s1 * (1.f/BATCH);
        float var = s2 * (1.f/BATCH) - mu*mu;
        float a = __ldg(&g0[t]) * rsqrtf(var + EPSN);
        g_a0[t] = a;
        g_c0[t] = __ldg(&bb0[t]) - mu * a;
    }
}

// ---------------- K5: mma.sync tf32 GEMM 32->4000 + sigmoid ----------------
__device__ __forceinline__ float sigf(float v) {
    float e, r;
    asm("ex2.approx.f32 %0, %1;" : "=f"(e) : "f"(-v * 1.442695041f));
    asm("rcp.approx.f32 %0, %1;" : "=f"(r) : "f"(1.0f + e));
    return r;
}
__device__ __forceinline__ uint32_t tf32c(float v) {
    uint32_t u;
    asm("cvt.rna.tf32.f32 %0, %1;" : "=r"(u) : "f"(v));
    return u;
}

// CTA tile 128M x 128N, K=32, 8 warps (4M x 2N), warp tile 32M x 64N.
// Smem holds A/B pre-scattered in m16n8k8 fragment order:
//   AF[msub(8)][kstep(4)][reg(4)][lane(32)]  (16 KB)
//   BF[nsub(16)][kstep(4)][reg(2)][lane(32)] (16 KB)
__global__ __launch_bounds__(256, 2) void k5_mma(
    const float* __restrict__ W2, const float* __restrict__ b2,
    float* __restrict__ out) {
    __shared__ uint32_t AF[8*4*4*32];
    __shared__ uint32_t BF[16*4*2*32];
    const int t = threadIdx.x;
    const int c  = blockIdx.z;
    const int m0 = blockIdx.y << 7;
    const int n0 = blockIdx.x << 7;

    // ---- producer A: zn (BN0+leaky on the fly) -> tf32 frags
    #pragma unroll
    for (int s = 0; s < 4; s++) {
        int i = t + s*256;            // 1024 float4s
        int row = i >> 3, q = i & 7;  // row in [0,128), q = k-quad
        float4 z4 = *(const float4*)&g_z[(size_t)(m0 + row)*CZ + c*32 + q*4];
        float4 a4 = *(const float4*)&g_a0[c*32 + q*4];
        float4 c4 = *(const float4*)&g_c0[c*32 + q*4];
        float v0 = fmaf(z4.x, a4.x, c4.x); v0 = v0 >= 0.f ? v0 : 0.2f*v0;
        float v1 = fmaf(z4.y, a4.y, c4.y); v1 = v1 >= 0.f ? v1 : 0.2f*v1;
        float v2 = fmaf(z4.z, a4.z, c4.z); v2 = v2 >= 0.f ? v2 : 0.2f*v2;
        float v3 = fmaf(z4.w, a4.w, c4.w); v3 = v3 >= 0.f ? v3 : 0.2f*v3;
        int msub = row >> 4, r = row & 15;
        int kstep = q >> 1;
        int reg = (r >= 8 ? 1 : 0) + ((q & 1) << 1);
        uint4 u = make_uint4(tf32c(v0), tf32c(v1), tf32c(v2), tf32c(v3));
        *(uint4*)&AF[(((msub*4 + kstep)*4 + reg)*32) + ((r & 7) << 2)] = u;
    }
    // ---- producer B: W2 rows -> tf32 frags (zero-pad n >= 4000)
    #pragma unroll
    for (int s = 0; s < 4; s++) {
        int i = t + s*256;
        int row = i >> 3, q = i & 7;  // row = output col o (local)
        int o = n0 + row;
        float4 w4 = make_float4(0.f, 0.f, 0.f, 0.f);
        if (o < NOUT)
            w4 = *(const float4*)&W2[((size_t)c*NOUT + o)*32 + q*4];
        int nsub = row >> 3;
        int kstep = q >> 1;
        int reg = q & 1;
        uint4 u = make_uint4(tf32c(w4.x), tf32c(w4.y), tf32c(w4.z), tf32c(w4.w));
        *(uint4*)&BF[(((nsub*4 + kstep)*2 + reg)*32) + ((row & 7) << 2)] = u;
    }
    __syncthreads();

    const int wid = t >> 5, l = t & 31;
    const int wm = wid & 3, wn = wid >> 2;

    float acc[2][8][4];
    #pragma unroll
    for (int ms = 0; ms < 2; ms++)
        #pragma unroll
        for (int ns = 0; ns < 8; ns++)
            #pragma unroll
            for (int r = 0; r < 4; r++) acc[ms][ns][r] = 0.f;

    #pragma unroll
    for (int kstep = 0; kstep < 4; kstep++) {
        uint32_t a[2][4];
        #pragma unroll
        for (int ms = 0; ms < 2; ms++) {
            int msub = wm*2 + ms;
            #pragma unroll
            for (int r = 0; r < 4; r++)
                a[ms][r] = AF[((msub*4 + kstep)*4 + r)*32 + l];
        }
        uint32_t b[8][2];
        #pragma unroll
        for (int ns = 0; ns < 8; ns++) {
            int nsub = wn*8 + ns;
            #pragma unroll
            for (int r = 0; r < 2; r++)
                b[ns][r] = BF[((nsub*4 + kstep)*2 + r)*32 + l];
        }
        #pragma unroll
        for (int ms = 0; ms < 2; ms++)
            #pragma unroll
            for (int ns = 0; ns < 8; ns++)
                asm volatile(
                    "mma.sync.aligned.m16n8k8.row.col.f32.tf32.tf32.f32 "
                    "{%0,%1,%2,%3}, {%4,%5,%6,%7}, {%8,%9}, {%0,%1,%2,%3};"
                    : "+f"(acc[ms][ns][0]), "+f"(acc[ms][ns][1]),
                      "+f"(acc[ms][ns][2]), "+f"(acc[ms][ns][3])
                    : "r"(a[ms][0]), "r"(a[ms][1]), "r"(a[ms][2]), "r"(a[ms][3]),
                      "r"(b[ns][0]), "r"(b[ns][1]));
    }

    // ---- epilogue: bias + sigmoid + store
    const float* brow = b2 + (size_t)c*NOUT;
    const int g = l >> 2, q4 = l & 3;
    #pragma unroll
    for (int ms = 0; ms < 2; ms++) {
        int m = m0 + wm*32 + ms*16 + g;
        float* orow0 = out + (size_t)m*OUTW + (size_t)c*NOUT;
        float* orow1 = orow0 + (size_t)8*OUTW;
        #pragma unroll
        for (int ns = 0; ns < 8; ns++) {
            int col = n0 + wn*64 + ns*8 + 2*q4;
            if (col < NOUT) {
                float2 bb = *(const float2*)&brow[col];
                float2 o0, o1;
                o0.x = sigf(acc[ms][ns][0] + bb.x);
                o0.y = sigf(acc[ms][ns][1] + bb.y);
                o1.x = sigf(acc[ms][ns][2] + bb.x);
                o1.y = sigf(acc[ms][ns][3] + bb.y);
                *(float2*)&orow0[col] = o0;
                *(float2*)&orow1[col] = o1;
            }
        }
    }
}

// ---------------- launch ---------------------------------------------------
extern "C" void kernel_launch(void* const* d_in, const int* in_sizes, int n_in,
                              void* d_out, int out_size) {
    const float* x   = (const float*)d_in[0];
    const float* W1  = (const float*)d_in[1];
    const float* b1  = (const float*)d_in[2];
    const float* g1  = (const float*)d_in[3];
    const float* be1 = (const float*)d_in[4];
    const float* W0  = (const float*)d_in[5];
    const float* b0  = (const float*)d_in[6];
    const float* g0  = (const float*)d_in[7];
    const float* bb0 = (const float*)d_in[8];
    const float* W2  = (const float*)d_in[9];
    const float* b2  = (const float*)d_in[10];
    float* out = (float*)d_out;

    k1_xstats<<<NB1, 256>>>(x);
    k2_bn1<<<1, 512>>>(W1, b1, g1, be1);
    k3_z<<<NB3, 256>>>(x, W1, b1, W0, b0);
    k4_bn0<<<1, 768>>>(g0, bb0);
    k5_mma<<<dim3((NOUT + 127)/128, BATCH/128, NC), 256>>>(W2, b2, out);
}

// round 4
// speedup vs baseline: 1.4053x; 1.0572x over previous
#include <cuda_runtime.h>
#include <cstdint>
#include <math.h>

#define BATCH 2048
#define LAT   16
#define NC    23
#define HID0  16
#define HID1  32
#define NOUT  4000
#define CH    (NC*HID0)   // 368
#define CZ    (NC*HID1)   // 736
#define OUTW  (NC*NOUT)   // 92000
#define EPSN  1e-5f

#define NB1 64
#define NB3 128
#define ROWS3 16

// ---------------- scratch (device globals; no allocation) ----------------
__device__ float g_p1[NB1][272];                  // per-block: sum_x[16], sum_xx[256]
__device__ __align__(16) float g_a1[CH], g_c1[CH];
__device__ __align__(16) float g_z[BATCH*CZ];     // pre-BN z   [2048, 736]
__device__ float g_p3[NB3][2*CZ];
__device__ __align__(16) float g_a0[CZ], g_c0[CZ];

// ---------------- K1: partial stats of x ----------------------------------
__global__ void k1_xstats(const float* __restrict__ x) {
    __shared__ float sx[32][LAT];
    int t = threadIdx.x;
    int r0 = blockIdx.x * 32;
    for (int i = t; i < 32*LAT; i += 256)
        sx[i >> 4][i & 15] = x[(r0 + (i >> 4))*LAT + (i & 15)];
    __syncthreads();
    int i = t >> 4, j = t & 15;
    float s = 0.f;
    #pragma unroll
    for (int r = 0; r < 32; r++) s += sx[r][i] * sx[r][j];
    g_p1[blockIdx.x][16 + t] = s;
    if (t < 16) {
        float sm = 0.f;
        #pragma unroll
        for (int r = 0; r < 32; r++) sm += sx[r][t];
        g_p1[blockIdx.x][t] = sm;
    }
}

// ---------------- K2: h-stats from x-stats (h linear in x) -----------------
__global__ void k2_bn1(const float* __restrict__ W1, const float* __restrict__ b1,
                       const float* __restrict__ g1, const float* __restrict__ be1) {
    __shared__ float raw[272];
    __shared__ float smu[16];
    __shared__ float scov[256];
    int t = threadIdx.x;                 // 512
    if (t < 272) {
        float s = 0.f;
        #pragma unroll 8
        for (int b = 0; b < NB1; b++) s += g_p1[b][t];
        raw[t] = s;
    }
    __syncthreads();
    if (t < 16) smu[t] = raw[t] * (1.f/BATCH);
    __syncthreads();
    if (t < 256) scov[t] = raw[16 + t] * (1.f/BATCH) - smu[t >> 4]*smu[t & 15];
    __syncthreads();
    for (int j = t; j < CH; j += 512) {
        float w[16];
        #pragma unroll
        for (int i = 0; i < 16; i++) w[i] = __ldg(&W1[j*16 + i]);
        float m = __ldg(&b1[j]);
        #pragma unroll
        for (int i = 0; i < 16; i++) m = fmaf(w[i], smu[i], m);
        float v = 0.f;
        #pragma unroll
        for (int i = 0; i < 16; i++) {
            float wi = w[i];
            #pragma unroll
            for (int k = 0; k < 16; k++) v = fmaf(wi * w[k], scov[i*16 + k], v);
        }
        float a = __ldg(&g1[j]) * rsqrtf(v + EPSN);
        g_a1[j] = a;
        g_c1[j] = __ldg(&be1[j]) - m * a;
    }
}

// ---------------- K3: BN1+leaky -> grouped 16->32 -> z + partial stats -----
__global__ __launch_bounds__(256) void k3_z(
    const float* __restrict__ x, const float* __restrict__ W1,
    const float* __restrict__ b1, const float* __restrict__ W0,
    const float* __restrict__ b0) {
    __shared__ __align__(16) float shn[ROWS3][CH];
    int t = threadIdx.x;
    int r0 = blockIdx.x * ROWS3;
    for (int idx = t; idx < ROWS3*CH; idx += 256) {
        int row = idx / CH, j = idx - row*CH;
        const float4* wp = (const float4*)(W1 + j*16);
        const float4* xp = (const float4*)(x + (size_t)(r0 + row)*16);
        float4 w0 = __ldg(wp+0), w1 = __ldg(wp+1), w2 = __ldg(wp+2), w3 = __ldg(wp+3);
        float4 x0 = __ldg(xp+0), x1 = __ldg(xp+1), x2 = __ldg(xp+2), x3 = __ldg(xp+3);
        float h = __ldg(&b1[j]);
        h = fmaf(w0.x,x0.x, fmaf(w0.y,x0.y, fmaf(w0.z,x0.z, fmaf(w0.w,x0.w, h))));
        h = fmaf(w1.x,x1.x, fmaf(w1.y,x1.y, fmaf(w1.z,x1.z, fmaf(w1.w,x1.w, h))));
        h = fmaf(w2.x,x2.x, fmaf(w2.y,x2.y, fmaf(w2.z,x2.z, fmaf(w2.w,x2.w, h))));
        h = fmaf(w3.x,x3.x, fmaf(w3.y,x3.y, fmaf(w3.z,x3.z, fmaf(w3.w,x3.w, h))));
        float v = fmaf(h, g_a1[j], g_c1[j]);
        shn[row][j] = v >= 0.f ? v : 0.2f*v;
    }
    __syncthreads();
    for (int cc = t; cc < CZ; cc += 256) {
        int c = cc >> 5, o = cc & 31;
        const float4* wp = (const float4*)(W0 + (size_t)(c*32 + o)*16);
        float4 w0 = __ldg(wp+0), w1 = __ldg(wp+1), w2 = __ldg(wp+2), w3 = __ldg(wp+3);
        float bb = __ldg(&b0[cc]);
        float s1 = 0.f, s2 = 0.f;
        #pragma unroll 4
        for (int row = 0; row < ROWS3; row++) {
            const float4* hp = (const float4*)&shn[row][c*16];
            float4 h0 = hp[0], h1 = hp[1], h2 = hp[2], h3 = hp[3];
            float z = bb;
            z = fmaf(w0.x,h0.x, fmaf(w0.y,h0.y, fmaf(w0.z,h0.z, fmaf(w0.w,h0.w, z))));
            z = fmaf(w1.x,h1.x, fmaf(w1.y,h1.y, fmaf(w1.z,h1.z, fmaf(w1.w,h1.w, z))));
            z = fmaf(w2.x,h2.x, fmaf(w2.y,h2.y, fmaf(w2.z,h2.z, fmaf(w2.w,h2.w, z))));
            z = fmaf(w3.x,h3.x, fmaf(w3.y,h3.y, fmaf(w3.z,h3.z, fmaf(w3.w,h3.w, z))));
            g_z[(size_t)(r0 + row)*CZ + cc] = z;
            s1 += z; s2 = fmaf(z, z, s2);
        }
        g_p3[blockIdx.x][cc]      = s1;
        g_p3[blockIdx.x][CZ + cc] = s2;
    }
}

// ---------------- K4: reduce z stats -> fused BN0 scale/shift --------------
__global__ void k4_bn0(const float* __restrict__ g0, const float* __restrict__ bb0) {
    int ch = blockIdx.x * 32 + threadIdx.x;     // 23 blocks x 32 threads
    float s1 = 0.f, s2 = 0.f;
    #pragma unroll 16
    for (int b = 0; b < NB3; b++) { s1 += g_p3[b][ch]; s2 += g_p3[b][CZ + ch]; }
    float mu  = s1 * (1.f/BATCH);
    float var = s2 * (1.f/BATCH) - mu*mu;
    float a = __ldg(&g0[ch]) * rsqrtf(var + EPSN);
    g_a0[ch] = a;
    g_c0[ch] = __ldg(&bb0[ch]) - mu * a;
}

// ---------------- K5: mma.sync tf32 GEMM 32->4000 + sigmoid ----------------
__device__ __forceinline__ float sigf(float v) {
    float e, r;
    asm("ex2.approx.f32 %0, %1;" : "=f"(e) : "f"(-v * 1.442695041f));
    asm("rcp.approx.f32 %0, %1;" : "=f"(r) : "f"(1.0f + e));
    return r;
}
__device__ __forceinline__ uint32_t tf32c(float v) {
    uint32_t u;
    asm("cvt.rna.tf32.f32 %0, %1;" : "=r"(u) : "f"(v));
    return u;
}

// CTA tile 64M x 64N, K=32, 4 warps (2M x 2N), warp tile 32M x 64... 32M x 32N.
// Smem holds A/B pre-scattered in m16n8k8 fragment order:
//   AF[msub(4)][kstep(4)][reg(4)][lane(32)]  (8 KB)
//   BF[nsub(8)][kstep(4)][reg(2)][lane(32)]  (8 KB)
// B columns are PERMUTED so each thread's c0/c1 from subtile pair (2j,2j+1)
// cover 4 contiguous output columns -> float4 epilogue stores.
//   logical (sub = 2j+e, p) <-> global col 16j + 4*(p>>1) + 2e + (p&1)
__global__ __launch_bounds__(128, 7) void k5_mma(
    const float* __restrict__ W2, const float* __restrict__ b2,
    float* __restrict__ out) {
    __shared__ uint32_t AF[4*4*4*32];
    __shared__ uint32_t BF[8*4*2*32];
    const int t = threadIdx.x;
    const int c  = blockIdx.z;
    const int m0 = blockIdx.y << 6;
    const int n0 = blockIdx.x << 6;

    // ---- producer A: zn (BN0+leaky on the fly) -> tf32 frags
    #pragma unroll
    for (int s = 0; s < 4; s++) {
        int i = t + s*128;            // 512 float4s
        int row = i >> 3, q = i & 7;  // row in [0,64), q = k-quad
        float4 z4 = *(const float4*)&g_z[(size_t)(m0 + row)*CZ + c*32 + q*4];
        float4 a4 = *(const float4*)&g_a0[c*32 + q*4];
        float4 c4 = *(const float4*)&g_c0[c*32 + q*4];
        float v0 = fmaf(z4.x, a4.x, c4.x); v0 = v0 >= 0.f ? v0 : 0.2f*v0;
        float v1 = fmaf(z4.y, a4.y, c4.y); v1 = v1 >= 0.f ? v1 : 0.2f*v1;
        float v2 = fmaf(z4.z, a4.z, c4.z); v2 = v2 >= 0.f ? v2 : 0.2f*v2;
        float v3 = fmaf(z4.w, a4.w, c4.w); v3 = v3 >= 0.f ? v3 : 0.2f*v3;
        int msub = row >> 4, r = row & 15;
        int kstep = q >> 1;
        int reg = (r >= 8 ? 1 : 0) + ((q & 1) << 1);
        uint4 u = make_uint4(tf32c(v0), tf32c(v1), tf32c(v2), tf32c(v3));
        *(uint4*)&AF[(((msub*4 + kstep)*4 + reg)*32) + ((r & 7) << 2)] = u;
    }
    // ---- producer B: W2 rows -> tf32 frags, col-permuted, zero-pad n>=4000
    #pragma unroll
    for (int s = 0; s < 4; s++) {
        int i = t + s*128;
        int gcol = i >> 3, q = i & 7;
        int o = n0 + gcol;
        float4 w4 = make_float4(0.f, 0.f, 0.f, 0.f);
        if (o < NOUT)
            w4 = *(const float4*)&W2[((size_t)c*NOUT + o)*32 + q*4];
        int j16 = gcol >> 4, rr = gcol & 15;
        int sub = 2*j16 + ((rr >> 1) & 1);
        int p   = 2*(rr >> 2) + (rr & 1);
        int kstep = q >> 1, reg = q & 1;
        uint4 u = make_uint4(tf32c(w4.x), tf32c(w4.y), tf32c(w4.z), tf32c(w4.w));
        *(uint4*)&BF[(((sub*4 + kstep)*2 + reg)*32) + (p << 2)] = u;
    }
    __syncthreads();

    const int wid = t >> 5, l = t & 31;
    const int wm = wid & 1, wn = wid >> 1;

    float acc[2][4][4];
    #pragma unroll
    for (int ms = 0; ms < 2; ms++)
        #pragma unroll
        for (int ns = 0; ns < 4; ns++)
            #pragma unroll
            for (int r = 0; r < 4; r++) acc[ms][ns][r] = 0.f;

    #pragma unroll
    for (int kstep = 0; kstep < 4; kstep++) {
        uint32_t a[2][4];
        #pragma unroll
        for (int ms = 0; ms < 2; ms++) {
            int msub = wm*2 + ms;
            #pragma unroll
            for (int r = 0; r < 4; r++)
                a[ms][r] = AF[((msub*4 + kstep)*4 + r)*32 + l];
        }
        uint32_t b[4][2];
        #pragma unroll
        for (int ns = 0; ns < 4; ns++) {
            int nsub = wn*4 + ns;
            #pragma unroll
            for (int r = 0; r < 2; r++)
                b[ns][r] = BF[((nsub*4 + kstep)*2 + r)*32 + l];
        }
        #pragma unroll
        for (int ms = 0; ms < 2; ms++)
            #pragma unroll
            for (int ns = 0; ns < 4; ns++)
                asm volatile(
                    "mma.sync.aligned.m16n8k8.row.col.f32.tf32.tf32.f32 "
                    "{%0,%1,%2,%3}, {%4,%5,%6,%7}, {%8,%9}, {%0,%1,%2,%3};"
                    : "+f"(acc[ms][ns][0]), "+f"(acc[ms][ns][1]),
                      "+f"(acc[ms][ns][2]), "+f"(acc[ms][ns][3])
                    : "r"(a[ms][0]), "r"(a[ms][1]), "r"(a[ms][2]), "r"(a[ms][3]),
                      "r"(b[ns][0]), "r"(b[ns][1]));
    }

    // ---- epilogue: bias + sigmoid + float4 stores (permuted col mapping)
    const float* brow = b2 + (size_t)c*NOUT;
    const int g = l >> 2, q4 = l & 3;
    #pragma unroll
    for (int ms = 0; ms < 2; ms++) {
        int m = m0 + wm*32 + ms*16 + g;
        float* orow0 = out + (size_t)m*OUTW + (size_t)c*NOUT;
        float* orow1 = orow0 + (size_t)8*OUTW;
        #pragma unroll
        for (int j = 0; j < 2; j++) {
            int col = n0 + wn*32 + 16*j + 4*q4;
            if (col < NOUT) {
                float4 bb = *(const float4*)&brow[col];
                float4 o0, o1;
                o0.x = sigf(acc[ms][2*j  ][0] + bb.x);
                o0.y = sigf(acc[ms][2*j  ][1] + bb.y);
                o0.z = sigf(acc[ms][2*j+1][0] + bb.z);
                o0.w = sigf(acc[ms][2*j+1][1] + bb.w);
                o1.x = sigf(acc[ms][2*j  ][2] + bb.x);
                o1.y = sigf(acc[ms][2*j  ][3] + bb.y);
                o1.z = sigf(acc[ms][2*j+1][2] + bb.z);
                o1.w = sigf(acc[ms][2*j+1][3] + bb.w);
                *(float4*)&orow0[col] = o0;
                *(float4*)&orow1[col] = o1;
            }
        }
    }
}

// ---------------- launch ---------------------------------------------------
extern "C" void kernel_launch(void* const* d_in, const int* in_sizes, int n_in,
                              void* d_out, int out_size) {
    const float* x   = (const float*)d_in[0];
    const float* W1  = (const float*)d_in[1];
    const float* b1  = (const float*)d_in[2];
    const float* g1  = (const float*)d_in[3];
    const float* be1 = (const float*)d_in[4];
    const float* W0  = (const float*)d_in[5];
    const float* b0  = (const float*)d_in[6];
    const float* g0  = (const float*)d_in[7];
    const float* bb0 = (const float*)d_in[8];
    const float* W2  = (const float*)d_in[9];
    const float* b2  = (const float*)d_in[10];
    float* out = (float*)d_out;

    k1_xstats<<<NB1, 256>>>(x);
    k2_bn1<<<1, 512>>>(W1, b1, g1, be1);
    k3_z<<<NB3, 256>>>(x, W1, b1, W0, b0);
    k4_bn0<<<NC, 32>>>(g0, bb0);
    k5_mma<<<dim3((NOUT + 63)/64, BATCH/64, NC), 128>>>(W2, b2, out);
}

// round 5
// speedup vs baseline: 1.8552x; 1.3201x over previous
#include <cuda_runtime.h>
#include <cstdint>
#include <math.h>

#define BATCH 2048
#define LAT   16
#define NC    23
#define HID0  16
#define HID1  32
#define NOUT  4000
#define CH    (NC*HID0)   // 368
#define CZ    (NC*HID1)   // 736
#define OUTW  (NC*NOUT)   // 92000
#define EPSN  1e-5f

#define NB1 64
#define NB3 128
#define ROWS3 16

#define TPT 9      // n-tiles (64 cols) per CTA in k5
#define NSTRIP 7   // 7*9*64 = 4032 >= 4000

// ---------------- scratch (device globals; no allocation) ----------------
__device__ float g_p1[NB1][272];                  // per-block: sum_x[16], sum_xx[256]
__device__ __align__(16) float g_z[BATCH*CZ];     // pre-BN z   [2048, 736]
__device__ float g_p3[NB3][2*CZ];
__device__ __align__(16) float g_a0[CZ], g_c0[CZ];

// ---------------- K1: partial stats of x ----------------------------------
__global__ void k1_xstats(const float* __restrict__ x) {
    __shared__ float sx[32][LAT];
    int t = threadIdx.x;
    int r0 = blockIdx.x * 32;
    for (int i = t; i < 32*LAT; i += 256)
        sx[i >> 4][i & 15] = x[(r0 + (i >> 4))*LAT + (i & 15)];
    __syncthreads();
    int i = t >> 4, j = t & 15;
    float s = 0.f;
    #pragma unroll
    for (int r = 0; r < 32; r++) s += sx[r][i] * sx[r][j];
    g_p1[blockIdx.x][16 + t] = s;
    if (t < 16) {
        float sm = 0.f;
        #pragma unroll
        for (int r = 0; r < 32; r++) sm += sx[r][t];
        g_p1[blockIdx.x][t] = sm;
    }
}

// ---------------- K3: fused BN1-coef + BN1+leaky + grouped 16->32 ----------
__global__ __launch_bounds__(256) void k3_z(
    const float* __restrict__ x, const float* __restrict__ W1,
    const float* __restrict__ b1, const float* __restrict__ g1,
    const float* __restrict__ be1, const float* __restrict__ W0,
    const float* __restrict__ b0) {
    __shared__ __align__(16) float shn[ROWS3][CH];
    __shared__ float raw[272];
    __shared__ float smu[16];
    __shared__ float scov[256];
    __shared__ float sa1[CH], sc1[CH];
    int t = threadIdx.x;
    int r0 = blockIdx.x * ROWS3;

    // ---- redundant per-block BN1 coefficient computation (cheap, L2-hot)
    for (int i = t; i < 272; i += 256) {
        float s = 0.f;
        #pragma unroll 8
        for (int b = 0; b < NB1; b++) s += g_p1[b][i];
        raw[i] = s;
    }
    __syncthreads();
    if (t < 16) smu[t] = raw[t] * (1.f/BATCH);
    __syncthreads();
    if (t < 256) scov[t] = raw[16 + t] * (1.f/BATCH) - smu[t >> 4]*smu[t & 15];
    __syncthreads();
    for (int j = t; j < CH; j += 256) {
        float w[16];
        #pragma unroll
        for (int i = 0; i < 16; i++) w[i] = __ldg(&W1[j*16 + i]);
        float m = __ldg(&b1[j]);
        #pragma unroll
        for (int i = 0; i < 16; i++) m = fmaf(w[i], smu[i], m);
        float v = 0.f;
        #pragma unroll
        for (int i = 0; i < 16; i++) {
            float wi = w[i];
            #pragma unroll
            for (int k = 0; k < 16; k++) v = fmaf(wi * w[k], scov[i*16 + k], v);
        }
        float a = __ldg(&g1[j]) * rsqrtf(v + EPSN);
        sa1[j] = a;
        sc1[j] = __ldg(&be1[j]) - m * a;
    }
    __syncthreads();

    // ---- hn = leaky(a1*h + c1)
    for (int idx = t; idx < ROWS3*CH; idx += 256) {
        int row = idx / CH, j = idx - row*CH;
        const float4* wp = (const float4*)(W1 + j*16);
        const float4* xp = (const float4*)(x + (size_t)(r0 + row)*16);
        float4 w0 = __ldg(wp+0), w1 = __ldg(wp+1), w2 = __ldg(wp+2), w3 = __ldg(wp+3);
        float4 x0 = __ldg(xp+0), x1 = __ldg(xp+1), x2 = __ldg(xp+2), x3 = __ldg(xp+3);
        float h = __ldg(&b1[j]);
        h = fmaf(w0.x,x0.x, fmaf(w0.y,x0.y, fmaf(w0.z,x0.z, fmaf(w0.w,x0.w, h))));
        h = fmaf(w1.x,x1.x, fmaf(w1.y,x1.y, fmaf(w1.z,x1.z, fmaf(w1.w,x1.w, h))));
        h = fmaf(w2.x,x2.x, fmaf(w2.y,x2.y, fmaf(w2.z,x2.z, fmaf(w2.w,x2.w, h))));
        h = fmaf(w3.x,x3.x, fmaf(w3.y,x3.y, fmaf(w3.z,x3.z, fmaf(w3.w,x3.w, h))));
        float v = fmaf(h, sa1[j], sc1[j]);
        shn[row][j] = v >= 0.f ? v : 0.2f*v;
    }
    __syncthreads();

    // ---- z = hn @ W0^T + partial stats
    for (int cc = t; cc < CZ; cc += 256) {
        int c = cc >> 5, o = cc & 31;
        const float4* wp = (const float4*)(W0 + (size_t)(c*32 + o)*16);
        float4 w0 = __ldg(wp+0), w1 = __ldg(wp+1), w2 = __ldg(wp+2), w3 = __ldg(wp+3);
        float bb = __ldg(&b0[cc]);
        float s1 = 0.f, s2 = 0.f;
        #pragma unroll 4
        for (int row = 0; row < ROWS3; row++) {
            const float4* hp = (const float4*)&shn[row][c*16];
            float4 h0 = hp[0], h1 = hp[1], h2 = hp[2], h3 = hp[3];
            float z = bb;
            z = fmaf(w0.x,h0.x, fmaf(w0.y,h0.y, fmaf(w0.z,h0.z, fmaf(w0.w,h0.w, z))));
            z = fmaf(w1.x,h1.x, fmaf(w1.y,h1.y, fmaf(w1.z,h1.z, fmaf(w1.w,h1.w, z))));
            z = fmaf(w2.x,h2.x, fmaf(w2.y,h2.y, fmaf(w2.z,h2.z, fmaf(w2.w,h2.w, z))));
            z = fmaf(w3.x,h3.x, fmaf(w3.y,h3.y, fmaf(w3.z,h3.z, fmaf(w3.w,h3.w, z))));
            g_z[(size_t)(r0 + row)*CZ + cc] = z;
            s1 += z; s2 = fmaf(z, z, s2);
        }
        g_p3[blockIdx.x][cc]      = s1;
        g_p3[blockIdx.x][CZ + cc] = s2;
    }
}

// ---------------- K4: reduce z stats -> fused BN0 scale/shift --------------
__global__ void k4_bn0(const float* __restrict__ g0, const float* __restrict__ bb0) {
    __shared__ float r1[8][32], r2[8][32];
    int c = blockIdx.x;                          // 23 blocks x 256 threads
    int ch = threadIdx.x & 31, sl = threadIdx.x >> 5;
    float s1 = 0.f, s2 = 0.f;
    #pragma unroll
    for (int k = 0; k < 16; k++) {
        int b = sl*16 + k;
        s1 += g_p3[b][c*32 + ch];
        s2 += g_p3[b][CZ + c*32 + ch];
    }
    r1[sl][ch] = s1; r2[sl][ch] = s2;
    __syncthreads();
    if (sl == 0) {
        #pragma unroll
        for (int k = 1; k < 8; k++) { s1 += r1[k][ch]; s2 += r2[k][ch]; }
        float mu  = s1 * (1.f/BATCH);
        float var = s2 * (1.f/BATCH) - mu*mu;
        float a = __ldg(&g0[c*32 + ch]) * rsqrtf(var + EPSN);
        g_a0[c*32 + ch] = a;
        g_c0[c*32 + ch] = __ldg(&bb0[c*32 + ch]) - mu * a;
    }
}

// ---------------- K5: pipelined mma.sync tf32 GEMM + sigmoid ---------------
__device__ __forceinline__ float sigf(float v) {
    float e, r;
    asm("ex2.approx.f32 %0, %1;" : "=f"(e) : "f"(-v * 1.442695041f));
    asm("rcp.approx.f32 %0, %1;" : "=f"(r) : "f"(1.0f + e));
    return r;
}
__device__ __forceinline__ uint32_t tf32c(float v) {
    uint32_t u;
    asm("cvt.rna.tf32.f32 %0, %1;" : "=r"(u) : "f"(v));
    return u;
}

// CTA: m-tile 64, strip of TPT n-tiles of 64, 4 warps (2M x 2N), warp 32x32.
// A fragments resident in smem for the whole CTA; B double-buffered, with
// B(t+1) register-prefetched during mainloop+epilogue of tile t.
__global__ __launch_bounds__(128, 6) void k5_mma(
    const float* __restrict__ W2, const float* __restrict__ b2,
    float* __restrict__ out) {
    __shared__ uint32_t AF[4*4*4*32];        // 8 KB
    __shared__ uint32_t BF[2][8*4*2*32];     // 16 KB
    const int t = threadIdx.x;
    const int c  = blockIdx.z;
    const int m0 = blockIdx.y << 6;
    const int strip = blockIdx.x;

    // ---- A producer: zn (BN0+leaky on the fly) -> tf32 frags (once per CTA)
    #pragma unroll
    for (int s = 0; s < 4; s++) {
        int i = t + s*128;
        int row = i >> 3, q = i & 7;
        float4 z4 = *(const float4*)&g_z[(size_t)(m0 + row)*CZ + c*32 + q*4];
        float4 a4 = *(const float4*)&g_a0[c*32 + q*4];
        float4 c4 = *(const float4*)&g_c0[c*32 + q*4];
        float v0 = fmaf(z4.x, a4.x, c4.x); v0 = v0 >= 0.f ? v0 : 0.2f*v0;
        float v1 = fmaf(z4.y, a4.y, c4.y); v1 = v1 >= 0.f ? v1 : 0.2f*v1;
        float v2 = fmaf(z4.z, a4.z, c4.z); v2 = v2 >= 0.f ? v2 : 0.2f*v2;
        float v3 = fmaf(z4.w, a4.w, c4.w); v3 = v3 >= 0.f ? v3 : 0.2f*v3;
        int msub = row >> 4, r = row & 15;
        int kstep = q >> 1;
        int reg = (r >= 8 ? 1 : 0) + ((q & 1) << 1);
        uint4 u = make_uint4(tf32c(v0), tf32c(v1), tf32c(v2), tf32c(v3));
        *(uint4*)&AF[(((msub*4 + kstep)*4 + reg)*32) + ((r & 7) << 2)] = u;
    }

    const int wid = t >> 5, l = t & 31;
    const int wm = wid & 1, wn = wid >> 1;
    const int g = l >> 2, q4 = l & 3;
    const float* brow = b2 + (size_t)c*NOUT;
    const float* w2c  = W2 + (size_t)c*NOUT*32;

    // producer-side per-thread constants (gcol,q per chunk s)
    const int pr_gcol = t >> 3;           // base col for s stepping: i = t + s*128 -> gcol = i>>3
    const int pr_q    = t & 7;

    // ---- prefetch B raw for tile 0
    float4 braw[4];
    {
        int n0 = strip*TPT*64;
        #pragma unroll
        for (int s = 0; s < 4; s++) {
            int gcol = pr_gcol + s*16;
            int o = n0 + gcol;
            braw[s] = (o < NOUT) ? *(const float4*)&w2c[(size_t)o*32 + pr_q*4]
                                 : make_float4(0.f, 0.f, 0.f, 0.f);
        }
    }

    for (int tt = 0; tt < TPT; tt++) {
        const int n0 = (strip*TPT + tt)*64;
        uint32_t* BFc = BF[tt & 1];

        // ---- scatter B(tt) frags to smem (col-permuted for float4 epilogue)
        #pragma unroll
        for (int s = 0; s < 4; s++) {
            int gcol = pr_gcol + s*16;
            int j16 = gcol >> 4, rr = gcol & 15;
            int sub = 2*j16 + ((rr >> 1) & 1);
            int p   = 2*(rr >> 2) + (rr & 1);
            int kstep = pr_q >> 1, reg = pr_q & 1;
            uint4 u = make_uint4(tf32c(braw[s].x), tf32c(braw[s].y),
                                 tf32c(braw[s].z), tf32c(braw[s].w));
            *(uint4*)&BFc[(((sub*4 + kstep)*2 + reg)*32) + (p << 2)] = u;
        }
        // ---- prefetch B(tt+1)
        if (tt + 1 < TPT) {
            int n1 = (strip*TPT + tt + 1)*64;
            #pragma unroll
            for (int s = 0; s < 4; s++) {
                int gcol = pr_gcol + s*16;
                int o = n1 + gcol;
                braw[s] = (o < NOUT) ? *(const float4*)&w2c[(size_t)o*32 + pr_q*4]
                                     : make_float4(0.f, 0.f, 0.f, 0.f);
            }
        }
        __syncthreads();

        // ---- mainloop
        float acc[2][4][4];
        #pragma unroll
        for (int ms = 0; ms < 2; ms++)
            #pragma unroll
            for (int ns = 0; ns < 4; ns++)
                #pragma unroll
                for (int r = 0; r < 4; r++) acc[ms][ns][r] = 0.f;

        #pragma unroll
        for (int kstep = 0; kstep < 4; kstep++) {
            uint32_t a[2][4];
            #pragma unroll
            for (int ms = 0; ms < 2; ms++) {
                int msub = wm*2 + ms;
                #pragma unroll
                for (int r = 0; r < 4; r++)
                    a[ms][r] = AF[((msub*4 + kstep)*4 + r)*32 + l];
            }
            uint32_t b[4][2];
            #pragma unroll
            for (int ns = 0; ns < 4; ns++) {
                int nsub = wn*4 + ns;
                #pragma unroll
                for (int r = 0; r < 2; r++)
                    b[ns][r] = BFc[((nsub*4 + kstep)*2 + r)*32 + l];
            }
            #pragma unroll
            for (int ms = 0; ms < 2; ms++)
                #pragma unroll
                for (int ns = 0; ns < 4; ns++)
                    asm volatile(
                        "mma.sync.aligned.m16n8k8.row.col.f32.tf32.tf32.f32 "
                        "{%0,%1,%2,%3}, {%4,%5,%6,%7}, {%8,%9}, {%0,%1,%2,%3};"
                        : "+f"(acc[ms][ns][0]), "+f"(acc[ms][ns][1]),
                          "+f"(acc[ms][ns][2]), "+f"(acc[ms][ns][3])
                        : "r"(a[ms][0]), "r"(a[ms][1]), "r"(a[ms][2]), "r"(a[ms][3]),
                          "r"(b[ns][0]), "r"(b[ns][1]));
        }

        // ---- epilogue: bias + sigmoid + float4 stores (overlaps prefetch)
        #pragma unroll
        for (int ms = 0; ms < 2; ms++) {
            int m = m0 + wm*32 + ms*16 + g;
            float* orow0 = out + (size_t)m*OUTW + (size_t)c*NOUT;
            float* orow1 = orow0 + (size_t)8*OUTW;
            #pragma unroll
            for (int j = 0; j < 2; j++) {
                int col = n0 + wn*32 + 16*j + 4*q4;
                if (col < NOUT) {
                    float4 bb = *(const float4*)&brow[col];
                    float4 o0, o1;
                    o0.x = sigf(acc[ms][2*j  ][0] + bb.x);
                    o0.y = sigf(acc[ms][2*j  ][1] + bb.y);
                    o0.z = sigf(acc[ms][2*j+1][0] + bb.z);
                    o0.w = sigf(acc[ms][2*j+1][1] + bb.w);
                    o1.x = sigf(acc[ms][2*j  ][2] + bb.x);
                    o1.y = sigf(acc[ms][2*j  ][3] + bb.y);
                    o1.z = sigf(acc[ms][2*j+1][2] + bb.z);
                    o1.w = sigf(acc[ms][2*j+1][3] + bb.w);
                    *(float4*)&orow0[col] = o0;
                    *(float4*)&orow1[col] = o1;
                }
            }
        }
    }
}

// ---------------- launch ---------------------------------------------------
extern "C" void kernel_launch(void* const* d_in, const int* in_sizes, int n_in,
                              void* d_out, int out_size) {
    const float* x   = (const float*)d_in[0];
    const float* W1  = (const float*)d_in[1];
    const float* b1  = (const float*)d_in[2];
    const float* g1  = (const float*)d_in[3];
    const float* be1 = (const float*)d_in[4];
    const float* W0  = (const float*)d_in[5];
    const float* b0  = (const float*)d_in[6];
    const float* g0  = (const float*)d_in[7];
    const float* bb0 = (const float*)d_in[8];
    const float* W2  = (const float*)d_in[9];
    const float* b2  = (const float*)d_in[10];
    float* out = (float*)d_out;

    k1_xstats<<<NB1, 256>>>(x);
    k3_z<<<NB3, 256>>>(x, W1, b1, g1, be1, W0, b0);
    k4_bn0<<<NC, 256>>>(g0, bb0);
    k5_mma<<<dim3(NSTRIP, BATCH/64, NC), 128>>>(W2, b2, out);
}

// round 6
// speedup vs baseline: 2.1954x; 1.1834x over previous
#include <cuda_runtime.h>
#include <cstdint>
#include <math.h>

#define BATCH 2048
#define LAT   16
#define NC    23
#define HID0  16
#define HID1  32
#define NOUT  4000
#define CH    (NC*HID0)   // 368
#define CZ    (NC*HID1)   // 736
#define OUTW  (NC*NOUT)   // 92000
#define EPSN  1e-5f

#define NB1 64
#define NB3 128
#define ROWS3 16

#define TPT 9      // n-tiles (64 cols) per CTA in k5
#define NSTRIP 7   // 7*9*64 = 4032 >= 4000

// ---------------- scratch (device globals; no allocation) ----------------
__device__ float g_p1[NB1][272];                  // per-block: sum_x[16], sum_xx[256]
__device__ __align__(16) float g_z[BATCH*CZ];     // pre-BN z   [2048, 736]
__device__ float g_p3[NB3][2*CZ];
__device__ __align__(16) float g_a0[CZ], g_c0[CZ];

// ---------------- K1: partial stats of x ----------------------------------
__global__ void k1_xstats(const float* __restrict__ x) {
    __shared__ float sx[32][LAT];
    int t = threadIdx.x;
    int r0 = blockIdx.x * 32;
    for (int i = t; i < 32*LAT; i += 256)
        sx[i >> 4][i & 15] = x[(r0 + (i >> 4))*LAT + (i & 15)];
    __syncthreads();
    int i = t >> 4, j = t & 15;
    float s = 0.f;
    #pragma unroll
    for (int r = 0; r < 32; r++) s += sx[r][i] * sx[r][j];
    g_p1[blockIdx.x][16 + t] = s;
    if (t < 16) {
        float sm = 0.f;
        #pragma unroll
        for (int r = 0; r < 32; r++) sm += sx[r][t];
        g_p1[blockIdx.x][t] = sm;
    }
}

// ---------------- K3: fused BN1-coef + BN1+leaky + grouped 16->32 ----------
__global__ __launch_bounds__(256) void k3_z(
    const float* __restrict__ x, const float* __restrict__ W1,
    const float* __restrict__ b1, const float* __restrict__ g1,
    const float* __restrict__ be1, const float* __restrict__ W0,
    const float* __restrict__ b0) {
    __shared__ __align__(16) float shn[ROWS3][CH];
    __shared__ float raw[272];
    __shared__ float smu[16];
    __shared__ float scov[256];
    __shared__ float sa1[CH], sc1[CH];
    int t = threadIdx.x;
    int r0 = blockIdx.x * ROWS3;

    for (int i = t; i < 272; i += 256) {
        float s = 0.f;
        #pragma unroll 8
        for (int b = 0; b < NB1; b++) s += g_p1[b][i];
        raw[i] = s;
    }
    __syncthreads();
    if (t < 16) smu[t] = raw[t] * (1.f/BATCH);
    __syncthreads();
    if (t < 256) scov[t] = raw[16 + t] * (1.f/BATCH) - smu[t >> 4]*smu[t & 15];
    __syncthreads();
    for (int j = t; j < CH; j += 256) {
        float w[16];
        #pragma unroll
        for (int i = 0; i < 16; i++) w[i] = __ldg(&W1[j*16 + i]);
        float m = __ldg(&b1[j]);
        #pragma unroll
        for (int i = 0; i < 16; i++) m = fmaf(w[i], smu[i], m);
        float v = 0.f;
        #pragma unroll
        for (int i = 0; i < 16; i++) {
            float wi = w[i];
            #pragma unroll
            for (int k = 0; k < 16; k++) v = fmaf(wi * w[k], scov[i*16 + k], v);
        }
        float a = __ldg(&g1[j]) * rsqrtf(v + EPSN);
        sa1[j] = a;
        sc1[j] = __ldg(&be1[j]) - m * a;
    }
    __syncthreads();

    for (int idx = t; idx < ROWS3*CH; idx += 256) {
        int row = idx / CH, j = idx - row*CH;
        const float4* wp = (const float4*)(W1 + j*16);
        const float4* xp = (const float4*)(x + (size_t)(r0 + row)*16);
        float4 w0 = __ldg(wp+0), w1 = __ldg(wp+1), w2 = __ldg(wp+2), w3 = __ldg(wp+3);
        float4 x0 = __ldg(xp+0), x1 = __ldg(xp+1), x2 = __ldg(xp+2), x3 = __ldg(xp+3);
        float h = __ldg(&b1[j]);
        h = fmaf(w0.x,x0.x, fmaf(w0.y,x0.y, fmaf(w0.z,x0.z, fmaf(w0.w,x0.w, h))));
        h = fmaf(w1.x,x1.x, fmaf(w1.y,x1.y, fmaf(w1.z,x1.z, fmaf(w1.w,x1.w, h))));
        h = fmaf(w2.x,x2.x, fmaf(w2.y,x2.y, fmaf(w2.z,x2.z, fmaf(w2.w,x2.w, h))));
        h = fmaf(w3.x,x3.x, fmaf(w3.y,x3.y, fmaf(w3.z,x3.z, fmaf(w3.w,x3.w, h))));
        float v = fmaf(h, sa1[j], sc1[j]);
        shn[row][j] = v >= 0.f ? v : 0.2f*v;
    }
    __syncthreads();

    for (int cc = t; cc < CZ; cc += 256) {
        int c = cc >> 5, o = cc & 31;
        const float4* wp = (const float4*)(W0 + (size_t)(c*32 + o)*16);
        float4 w0 = __ldg(wp+0), w1 = __ldg(wp+1), w2 = __ldg(wp+2), w3 = __ldg(wp+3);
        float bb = __ldg(&b0[cc]);
        float s1 = 0.f, s2 = 0.f;
        #pragma unroll 4
        for (int row = 0; row < ROWS3; row++) {
            const float4* hp = (const float4*)&shn[row][c*16];
            float4 h0 = hp[0], h1 = hp[1], h2 = hp[2], h3 = hp[3];
            float z = bb;
            z = fmaf(w0.x,h0.x, fmaf(w0.y,h0.y, fmaf(w0.z,h0.z, fmaf(w0.w,h0.w, z))));
            z = fmaf(w1.x,h1.x, fmaf(w1.y,h1.y, fmaf(w1.z,h1.z, fmaf(w1.w,h1.w, z))));
            z = fmaf(w2.x,h2.x, fmaf(w2.y,h2.y, fmaf(w2.z,h2.z, fmaf(w2.w,h2.w, z))));
            z = fmaf(w3.x,h3.x, fmaf(w3.y,h3.y, fmaf(w3.z,h3.z, fmaf(w3.w,h3.w, z))));
            g_z[(size_t)(r0 + row)*CZ + cc] = z;
            s1 += z; s2 = fmaf(z, z, s2);
        }
        g_p3[blockIdx.x][cc]      = s1;
        g_p3[blockIdx.x][CZ + cc] = s2;
    }
}

// ---------------- K4: reduce z stats -> fused BN0 scale/shift --------------
__global__ void k4_bn0(const float* __restrict__ g0, const float* __restrict__ bb0) {
    __shared__ float r1[8][32], r2[8][32];
    int c = blockIdx.x;                          // 23 blocks x 256 threads
    int ch = threadIdx.x & 31, sl = threadIdx.x >> 5;
    float s1 = 0.f, s2 = 0.f;
    #pragma unroll
    for (int k = 0; k < 16; k++) {
        int b = sl*16 + k;
        s1 += g_p3[b][c*32 + ch];
        s2 += g_p3[b][CZ + c*32 + ch];
    }
    r1[sl][ch] = s1; r2[sl][ch] = s2;
    __syncthreads();
    if (sl == 0) {
        #pragma unroll
        for (int k = 1; k < 8; k++) { s1 += r1[k][ch]; s2 += r2[k][ch]; }
        float mu  = s1 * (1.f/BATCH);
        float var = s2 * (1.f/BATCH) - mu*mu;
        float a = __ldg(&g0[c*32 + ch]) * rsqrtf(var + EPSN);
        g_a0[c*32 + ch] = a;
        g_c0[c*32 + ch] = __ldg(&bb0[c*32 + ch]) - mu * a;
    }
}

// ---------------- K5: pipelined mma.sync tf32 GEMM + sigmoid ---------------
__device__ __forceinline__ float sigf(float v) {
    float e, r;
    asm("ex2.approx.f32 %0, %1;" : "=f"(e) : "f"(-v * 1.442695041f));
    asm("rcp.approx.f32 %0, %1;" : "=f"(r) : "f"(1.0f + e));
    return r;
}
__device__ __forceinline__ uint32_t tf32c(float v) {
    uint32_t u;
    asm("cvt.rna.tf32.f32 %0, %1;" : "=r"(u) : "f"(v));
    return u;
}

// CTA: m-tile 64, strip of TPT n-tiles of 64, 4 warps (2M x 2N), warp 32x32.
// A fragments live in REGISTERS for the whole strip (loaded once from smem).
// B double-buffered in smem, XOR-swizzled so the producer scatter STS.128 is
// bank-conflict-free: physical 16B slot p_phys = p ^ (row & 7).
//   write: byte = row*128 + (p ^ (row&7))*16        (row&7 == q on write side)
//   read : lane l, c = row&7: byte = row*128 + ((l*4) ^ (c*16))
__global__ __launch_bounds__(128, 5) void k5_mma(
    const float* __restrict__ W2, const float* __restrict__ b2,
    float* __restrict__ out) {
    __shared__ uint32_t AF[4*4*4*32];        // 8 KB
    __shared__ uint32_t BF[2][8*4*2*32];     // 16 KB
    const int t = threadIdx.x;
    const int c  = blockIdx.z;
    const int m0 = blockIdx.y << 6;
    const int strip = blockIdx.x;

    // ---- A producer: zn (BN0+leaky on the fly) -> tf32 frags (once per CTA)
    #pragma unroll
    for (int s = 0; s < 4; s++) {
        int i = t + s*128;
        int row = i >> 3, q = i & 7;
        float4 z4 = *(const float4*)&g_z[(size_t)(m0 + row)*CZ + c*32 + q*4];
        float4 a4 = *(const float4*)&g_a0[c*32 + q*4];
        float4 c4 = *(const float4*)&g_c0[c*32 + q*4];
        float v0 = fmaf(z4.x, a4.x, c4.x); v0 = v0 >= 0.f ? v0 : 0.2f*v0;
        float v1 = fmaf(z4.y, a4.y, c4.y); v1 = v1 >= 0.f ? v1 : 0.2f*v1;
        float v2 = fmaf(z4.z, a4.z, c4.z); v2 = v2 >= 0.f ? v2 : 0.2f*v2;
        float v3 = fmaf(z4.w, a4.w, c4.w); v3 = v3 >= 0.f ? v3 : 0.2f*v3;
        int msub = row >> 4, r = row & 15;
        int kstep = q >> 1;
        int reg = (r >= 8 ? 1 : 0) + ((q & 1) << 1);
        uint4 u = make_uint4(tf32c(v0), tf32c(v1), tf32c(v2), tf32c(v3));
        *(uint4*)&AF[(((msub*4 + kstep)*4 + reg)*32) + ((r & 7) << 2)] = u;
    }
    __syncthreads();

    const int wid = t >> 5, l = t & 31;
    const int wm = wid & 1, wn = wid >> 1;
    const int g = l >> 2, q4 = l & 3;
    const float* brow = b2 + (size_t)c*NOUT;
    const float* w2c  = W2 + (size_t)c*NOUT*32;

    // ---- A fragments into registers for the whole strip
    uint32_t areg[2][4][4];
    #pragma unroll
    for (int ms = 0; ms < 2; ms++)
        #pragma unroll
        for (int kstep = 0; kstep < 4; kstep++)
            #pragma unroll
            for (int r = 0; r < 4; r++)
                areg[ms][kstep][r] = AF[(((wm*2 + ms)*4 + kstep)*4 + r)*32 + l];

    const int pr_gcol = t >> 3;
    const int pr_q    = t & 7;
    const int l4      = l << 2;

    // ---- prefetch B raw for tile 0
    float4 braw[4];
    {
        int n0 = strip*TPT*64;
        #pragma unroll
        for (int s = 0; s < 4; s++) {
            int gcol = pr_gcol + s*16;
            int o = n0 + gcol;
            braw[s] = (o < NOUT) ? *(const float4*)&w2c[(size_t)o*32 + pr_q*4]
                                 : make_float4(0.f, 0.f, 0.f, 0.f);
        }
    }

    for (int tt = 0; tt < TPT; tt++) {
        const int n0 = (strip*TPT + tt)*64;
        char* BFc = (char*)BF[tt & 1];

        // ---- scatter B(tt) frags to smem, swizzled (conflict-free STS.128)
        #pragma unroll
        for (int s = 0; s < 4; s++) {
            int gcol = pr_gcol + s*16;
            int j16 = gcol >> 4, rr = gcol & 15;
            int sub = 2*j16 + ((rr >> 1) & 1);
            int p   = 2*(rr >> 2) + (rr & 1);
            int row = sub*8 + pr_q;              // row&7 == pr_q
            int pp  = p ^ pr_q;
            uint4 u = make_uint4(tf32c(braw[s].x), tf32c(braw[s].y),
                                 tf32c(braw[s].z), tf32c(braw[s].w));
            *(uint4*)(BFc + row*128 + pp*16) = u;
        }
        // ---- prefetch B(tt+1)
        if (tt + 1 < TPT) {
            int n1 = (strip*TPT + tt + 1)*64;
            #pragma unroll
            for (int s = 0; s < 4; s++) {
                int gcol = pr_gcol + s*16;
                int o = n1 + gcol;
                braw[s] = (o < NOUT) ? *(const float4*)&w2c[(size_t)o*32 + pr_q*4]
                                     : make_float4(0.f, 0.f, 0.f, 0.f);
            }
        }
        __syncthreads();

        // ---- mainloop: B LDS (swizzled, conflict-free) + HMMA
        float acc[2][4][4];
        #pragma unroll
        for (int ms = 0; ms < 2; ms++)
            #pragma unroll
            for (int ns = 0; ns < 4; ns++)
                #pragma unroll
                for (int r = 0; r < 4; r++) acc[ms][ns][r] = 0.f;

        const char* bbase = BFc + wn*4096;
        #pragma unroll
        for (int kstep = 0; kstep < 4; kstep++) {
            uint32_t b[4][2];
            #pragma unroll
            for (int ns = 0; ns < 4; ns++) {
                #pragma unroll
                for (int r = 0; r < 2; r++) {
                    const int cc = kstep*2 + r;
                    b[ns][r] = *(const uint32_t*)(bbase + ns*1024 + cc*128
                                                  + (l4 ^ (cc << 4)));
                }
            }
            #pragma unroll
            for (int ms = 0; ms < 2; ms++)
                #pragma unroll
                for (int ns = 0; ns < 4; ns++)
                    asm volatile(
                        "mma.sync.aligned.m16n8k8.row.col.f32.tf32.tf32.f32 "
                        "{%0,%1,%2,%3}, {%4,%5,%6,%7}, {%8,%9}, {%0,%1,%2,%3};"
                        : "+f"(acc[ms][ns][0]), "+f"(acc[ms][ns][1]),
                          "+f"(acc[ms][ns][2]), "+f"(acc[ms][ns][3])
                        : "r"(areg[ms][kstep][0]), "r"(areg[ms][kstep][1]),
                          "r"(areg[ms][kstep][2]), "r"(areg[ms][kstep][3]),
                          "r"(b[ns][0]), "r"(b[ns][1]));
        }

        // ---- epilogue: bias + sigmoid + float4 stores
        #pragma unroll
        for (int ms = 0; ms < 2; ms++) {
            int m = m0 + wm*32 + ms*16 + g;
            float* orow0 = out + (size_t)m*OUTW + (size_t)c*NOUT;
            float* orow1 = orow0 + (size_t)8*OUTW;
            #pragma unroll
            for (int j = 0; j < 2; j++) {
                int col = n0 + wn*32 + 16*j + 4*q4;
                if (col < NOUT) {
                    float4 bb = *(const float4*)&brow[col];
                    float4 o0, o1;
                    o0.x = sigf(acc[ms][2*j  ][0] + bb.x);
                    o0.y = sigf(acc[ms][2*j  ][1] + bb.y);
                    o0.z = sigf(acc[ms][2*j+1][0] + bb.z);
                    o0.w = sigf(acc[ms][2*j+1][1] + bb.w);
                    o1.x = sigf(acc[ms][2*j  ][2] + bb.x);
                    o1.y = sigf(acc[ms][2*j  ][3] + bb.y);
                    o1.z = sigf(acc[ms][2*j+1][2] + bb.z);
                    o1.w = sigf(acc[ms][2*j+1][3] + bb.w);
                    *(float4*)&orow0[col] = o0;
                    *(float4*)&orow1[col] = o1;
                }
            }
        }
    }
}

// ---------------- launch ---------------------------------------------------
extern "C" void kernel_launch(void* const* d_in, const int* in_sizes, int n_in,
                              void* d_out, int out_size) {
    const float* x   = (const float*)d_in[0];
    const float* W1  = (const float*)d_in[1];
    const float* b1  = (const float*)d_in[2];
    const float* g1  = (const float*)d_in[3];
    const float* be1 = (const float*)d_in[4];
    const float* W0  = (const float*)d_in[5];
    const float* b0  = (const float*)d_in[6];
    const float* g0  = (const float*)d_in[7];
    const float* bb0 = (const float*)d_in[8];
    const float* W2  = (const float*)d_in[9];
    const float* b2  = (const float*)d_in[10];
    float* out = (float*)d_out;

    k1_xstats<<<NB1, 256>>>(x);
    k3_z<<<NB3, 256>>>(x, W1, b1, g1, be1, W0, b0);
    k4_bn0<<<NC, 256>>>(g0, bb0);
    k5_mma<<<dim3(NSTRIP, BATCH/64, NC), 128>>>(W2, b2, out);
}